// round 1
// baseline (speedup 1.0000x reference)
#include <cuda_runtime.h>

#define NN   2048
#define EE   262144
#define SD   256
#define VD   64
#define ED   32
#define NMOL 64
#define NAF  16
#define NBT  5

// ---- scratch (device globals; no allocations) ----
__device__ float g_sh[NN * SD];        // s_h = silu(s@Ws+bs)
__device__ float g_G[NN * SD];         // G = s_h @ W0[0:256,:]
__device__ float g_cpraw[NN * 3];      // p + v@Wc
__device__ float g_cp[NN * 3];         // centered coords
__device__ float g_molmean[NMOL * 3];
__device__ float g_M[ED * SD];         // M = Wb @ W0a
__device__ float g_c0[SD];             // c0 = b0 + bb @ W0a
__device__ int   g_map[NN * NN];       // last-edge-index map (dense scatter)

__device__ __forceinline__ float silu_f(float x) {
    return x / (1.0f + __expf(-x));
}

// ---- K0: clear map ----
__global__ void k_clear() {
    int i = blockIdx.x * blockDim.x + threadIdx.x;
    int stride = gridDim.x * blockDim.x;
    for (; i < NN * NN; i += stride) g_map[i] = -1;
}

// ---- K5: scatter last-edge-wins (atomicMax over edge index == sequential last write) ----
__global__ void k_scatter(const int* __restrict__ eg) {
    int k = blockIdx.x * blockDim.x + threadIdx.x;
    if (k < EE) {
        int j = eg[k];
        int i = eg[EE + k];
        atomicMax(&g_map[j * NN + i], k);
    }
}

// ---- K1: s_h = silu(s@Ws+bs), cpraw = p + v@Wc.  8 nodes per CTA. ----
__global__ __launch_bounds__(256) void k_node1(
    const float* __restrict__ s, const float* __restrict__ v,
    const float* __restrict__ p, const float* __restrict__ Ws,
    const float* __restrict__ bs, const float* __restrict__ Wc)
{
    __shared__ float ss[8][SD];
    const int t = threadIdx.x;
    const int n0 = blockIdx.x * 8;
    #pragma unroll
    for (int r = 0; r < 8; r++) ss[r][t] = s[(n0 + r) * SD + t];
    __syncthreads();

    float acc[8];
    #pragma unroll
    for (int r = 0; r < 8; r++) acc[r] = 0.0f;

    for (int k = 0; k < SD; k += 4) {
        float w0 = Ws[(k + 0) * SD + t];
        float w1 = Ws[(k + 1) * SD + t];
        float w2 = Ws[(k + 2) * SD + t];
        float w3 = Ws[(k + 3) * SD + t];
        #pragma unroll
        for (int r = 0; r < 8; r++) {
            float4 a = *(const float4*)&ss[r][k];
            acc[r] += a.x * w0;
            acc[r] += a.y * w1;
            acc[r] += a.z * w2;
            acc[r] += a.w * w3;
        }
    }
    float b = bs[t];
    #pragma unroll
    for (int r = 0; r < 8; r++) {
        g_sh[(n0 + r) * SD + t] = silu_f(acc[r] + b);
    }

    if (t < 24) {  // 8 nodes x 3 axes
        int r = t / 3, x = t % 3;
        const float* vp = &v[(n0 + r) * 3 * VD + x * VD];
        float sum = 0.0f;
        #pragma unroll 8
        for (int q = 0; q < VD; q++) sum += vp[q] * Wc[q];
        g_cpraw[(n0 + r) * 3 + x] = p[(n0 + r) * 3 + x] + sum;
    }
}

// ---- K2: M = Wb@W0a (rows 0..31), c0 = b0 + bb@W0a (block 32) ----
__global__ __launch_bounds__(256) void k_mw(
    const float* __restrict__ Wb, const float* __restrict__ bb,
    const float* __restrict__ W0, const float* __restrict__ b0)
{
    __shared__ float row[SD];
    const int t = threadIdx.x;
    const int q = blockIdx.x;
    row[t] = (q < ED) ? Wb[q * SD + t] : bb[t];
    __syncthreads();

    float acc = 0.0f;
    for (int k = 0; k < SD; k += 4) {
        float4 a = *(const float4*)&row[k];
        acc += a.x * W0[(k + 0) * SD + t];
        acc += a.y * W0[(k + 1) * SD + t];
        acc += a.z * W0[(k + 2) * SD + t];
        acc += a.w * W0[(k + 3) * SD + t];
    }
    if (q < ED) g_M[q * SD + t] = acc;
    else        g_c0[t] = b0[t] + acc;
}

// ---- K3a: per-mol mean (deterministic fixed-tree reduction) ----
__global__ void k_molmean(const int* __restrict__ batch) {
    __shared__ float red[128][4];
    const int b = blockIdx.x;
    const int t = threadIdx.x;
    float sx = 0.f, sy = 0.f, sz = 0.f, c = 0.f;
    for (int n = t; n < NN; n += 128) {
        if (batch[n] == b) {
            sx += g_cpraw[n * 3 + 0];
            sy += g_cpraw[n * 3 + 1];
            sz += g_cpraw[n * 3 + 2];
            c  += 1.0f;
        }
    }
    red[t][0] = sx; red[t][1] = sy; red[t][2] = sz; red[t][3] = c;
    __syncthreads();
    for (int s = 64; s > 0; s >>= 1) {
        if (t < s) {
            red[t][0] += red[t + s][0];
            red[t][1] += red[t + s][1];
            red[t][2] += red[t + s][2];
            red[t][3] += red[t + s][3];
        }
        __syncthreads();
    }
    if (t < 3) g_molmean[b * 3 + t] = red[0][t] / fmaxf(red[0][3], 1.0f);
}

// ---- K3b: center coords + write output ----
__global__ void k_center(const int* __restrict__ batch, float* __restrict__ out_coords) {
    int n = blockIdx.x * blockDim.x + threadIdx.x;
    if (n < NN) {
        int b = batch[n];
        #pragma unroll
        for (int x = 0; x < 3; x++) {
            float cpv = g_cpraw[n * 3 + x] - g_molmean[b * 3 + x];
            g_cp[n * 3 + x] = cpv;
            out_coords[n * 3 + x] = cpv;
        }
    }
}

// ---- K4: G = s_h@W0a and atoms_pred = s_h@Wa + ba ----
__global__ __launch_bounds__(256) void k_node2(
    const float* __restrict__ W0, const float* __restrict__ Wa,
    const float* __restrict__ ba, float* __restrict__ out_atoms)
{
    __shared__ float sh[8][SD];
    const int t = threadIdx.x;
    const int n0 = blockIdx.x * 8;
    #pragma unroll
    for (int r = 0; r < 8; r++) sh[r][t] = g_sh[(n0 + r) * SD + t];
    __syncthreads();

    float acc[8];
    #pragma unroll
    for (int r = 0; r < 8; r++) acc[r] = 0.0f;
    for (int k = 0; k < SD; k += 4) {
        float w0 = W0[(k + 0) * SD + t];
        float w1 = W0[(k + 1) * SD + t];
        float w2 = W0[(k + 2) * SD + t];
        float w3 = W0[(k + 3) * SD + t];
        #pragma unroll
        for (int r = 0; r < 8; r++) {
            float4 a = *(const float4*)&sh[r][k];
            acc[r] += a.x * w0;
            acc[r] += a.y * w1;
            acc[r] += a.z * w2;
            acc[r] += a.w * w3;
        }
    }
    #pragma unroll
    for (int r = 0; r < 8; r++) g_G[(n0 + r) * SD + t] = acc[r];

    if (t < 8 * NAF) {  // 128 threads: 8 nodes x 16 features
        int r = t >> 4, a = t & 15;
        float sum = 0.0f;
        for (int k = 0; k < SD; k++) sum += sh[r][k] * Wa[k * NAF + a];
        out_atoms[(n0 + r) * NAF + a] = sum + ba[a];
    }
}

// ---- K6: fused edge kernel: 64 edges per CTA ----
// z = c0 + e_sym@M + G[i] + G[j] + d*W0[256,:];  bonds = silu(z)@W1 + b1
__global__ __launch_bounds__(256, 2) void k_edge(
    const int* __restrict__ eg, const float* __restrict__ efeat,
    const float* __restrict__ W0, const float* __restrict__ W1,
    const float* __restrict__ b1, float* __restrict__ out_bonds)
{
    __shared__ float sM[ED][SD];       // 32 KB
    __shared__ float sE[64][ED + 1];   // e_sym tile, 8.25 KB
    __shared__ int   sI[64], sJ[64], sKa[64], sKb[64];
    __shared__ float sD[64];

    const int t = threadIdx.x;
    const int base = blockIdx.x * 64;

    {   // stage M into smem (8192 floats = 2048 float4)
        const float4* src = (const float4*)g_M;
        float4* dst = (float4*)sM;
        #pragma unroll
        for (int r = 0; r < 8; r++) dst[t + 256 * r] = src[t + 256 * r];
    }
    if (t < 64) {
        int eid = base + t;
        int j = eg[eid], i = eg[EE + eid];
        sI[t] = i; sJ[t] = j;
        sKa[t] = g_map[j * NN + i];
        sKb[t] = g_map[i * NN + j];
        float dx = g_cp[i * 3 + 0] - g_cp[j * 3 + 0];
        float dy = g_cp[i * 3 + 1] - g_cp[j * 3 + 1];
        float dz = g_cp[i * 3 + 2] - g_cp[j * 3 + 2];
        sD[t] = dx * dx + dy * dy + dz * dz;
    }
    __syncthreads();

    // build e_sym = 0.5*(e[ka] + (kb>=0 ? e[kb] : 0))
    #pragma unroll
    for (int r = 0; r < 8; r++) {
        int idx = t + 256 * r;
        int m = idx >> 5, q = idx & 31;
        int ka = sKa[m], kb = sKb[m];
        float vv = efeat[ka * ED + q];
        if (kb >= 0) vv += efeat[kb * ED + q];
        sE[m][q] = 0.5f * vv;
    }
    __syncthreads();

    const int ng = t & 15;        // 16 column-groups of 16 hidden cols
    const int mg = t >> 4;        // 16 row-groups of 4 edges
    const int ccol = ng * 16;

    float acc[4][16];
    {   // init with c0 (= b0 + bb@W0a)
        float4 c0v[4];
        #pragma unroll
        for (int u4 = 0; u4 < 4; u4++) c0v[u4] = *(const float4*)&g_c0[ccol + u4 * 4];
        #pragma unroll
        for (int r = 0; r < 4; r++) {
            #pragma unroll
            for (int u4 = 0; u4 < 4; u4++) {
                acc[r][u4 * 4 + 0] = c0v[u4].x;
                acc[r][u4 * 4 + 1] = c0v[u4].y;
                acc[r][u4 * 4 + 2] = c0v[u4].z;
                acc[r][u4 * 4 + 3] = c0v[u4].w;
            }
        }
    }

    // main GEMM: [64,32] @ [32,256], per-thread 4x16 micro-tile
    #pragma unroll 8
    for (int k = 0; k < ED; k++) {
        float a0 = sE[mg * 4 + 0][k];
        float a1 = sE[mg * 4 + 1][k];
        float a2 = sE[mg * 4 + 2][k];
        float a3 = sE[mg * 4 + 3][k];
        float wv[16];
        #pragma unroll
        for (int u4 = 0; u4 < 4; u4++) {
            float4 w = *(const float4*)&sM[k][ccol + u4 * 4];
            wv[u4 * 4 + 0] = w.x; wv[u4 * 4 + 1] = w.y;
            wv[u4 * 4 + 2] = w.z; wv[u4 * 4 + 3] = w.w;
        }
        #pragma unroll
        for (int u = 0; u < 16; u++) {
            acc[0][u] += a0 * wv[u];
            acc[1][u] += a1 * wv[u];
            acc[2][u] += a2 * wv[u];
            acc[3][u] += a3 * wv[u];
        }
    }

    // add G[i] + G[j] + d * W0[256,:]
    float wd[16];
    {
        const float* wdp = W0 + (size_t)SD * SD;   // row 256 of W0 [257,256]
        #pragma unroll
        for (int u4 = 0; u4 < 4; u4++) {
            float4 w = *(const float4*)&wdp[ccol + u4 * 4];
            wd[u4 * 4 + 0] = w.x; wd[u4 * 4 + 1] = w.y;
            wd[u4 * 4 + 2] = w.z; wd[u4 * 4 + 3] = w.w;
        }
    }
    #pragma unroll
    for (int r = 0; r < 4; r++) {
        int m = mg * 4 + r;
        const float4* Gi = (const float4*)&g_G[sI[m] * SD + ccol];
        const float4* Gj = (const float4*)&g_G[sJ[m] * SD + ccol];
        float dm = sD[m];
        #pragma unroll
        for (int u4 = 0; u4 < 4; u4++) {
            float4 a = Gi[u4];
            float4 b = Gj[u4];
            acc[r][u4 * 4 + 0] += a.x + b.x + dm * wd[u4 * 4 + 0];
            acc[r][u4 * 4 + 1] += a.y + b.y + dm * wd[u4 * 4 + 1];
            acc[r][u4 * 4 + 2] += a.z + b.z + dm * wd[u4 * 4 + 2];
            acc[r][u4 * 4 + 3] += a.w + b.w + dm * wd[u4 * 4 + 3];
        }
    }

    // silu + second GEMM [*,256]@[256,5] (partial over this thread's 16 cols)
    float pb[4][NBT];
    #pragma unroll
    for (int r = 0; r < 4; r++)
        #pragma unroll
        for (int b = 0; b < NBT; b++) pb[r][b] = 0.0f;

    #pragma unroll
    for (int u = 0; u < 16; u++) {
        int cc = ccol + u;
        float w1r[NBT];
        #pragma unroll
        for (int b = 0; b < NBT; b++) w1r[b] = __ldg(&W1[cc * NBT + b]);
        #pragma unroll
        for (int r = 0; r < 4; r++) {
            float h = silu_f(acc[r][u]);
            #pragma unroll
            for (int b = 0; b < NBT; b++) pb[r][b] += h * w1r[b];
        }
    }

    // reduce over the 16 column-groups (16-lane shuffle segments)
    for (int off = 8; off >= 1; off >>= 1) {
        #pragma unroll
        for (int r = 0; r < 4; r++)
            #pragma unroll
            for (int b = 0; b < NBT; b++)
                pb[r][b] += __shfl_down_sync(0xffffffffu, pb[r][b], off, 16);
    }
    if (ng == 0) {
        #pragma unroll
        for (int r = 0; r < 4; r++) {
            int eid = base + mg * 4 + r;
            #pragma unroll
            for (int b = 0; b < NBT; b++)
                out_bonds[eid * NBT + b] = pb[r][b] + __ldg(&b1[b]);
        }
    }
}

extern "C" void kernel_launch(void* const* d_in, const int* in_sizes, int n_in,
                              void* d_out, int out_size)
{
    const float* s     = (const float*)d_in[0];
    const float* v     = (const float*)d_in[1];
    const float* p     = (const float*)d_in[2];
    const float* e     = (const float*)d_in[3];
    const int*   batch = (const int*)  d_in[4];
    const int*   eg    = (const int*)  d_in[5];
    const float* Ws    = (const float*)d_in[6];
    const float* bs    = (const float*)d_in[7];
    const float* Wc    = (const float*)d_in[8];
    const float* Wa    = (const float*)d_in[9];
    const float* ba    = (const float*)d_in[10];
    const float* Wb    = (const float*)d_in[11];
    const float* bb    = (const float*)d_in[12];
    const float* W0    = (const float*)d_in[13];
    const float* b0    = (const float*)d_in[14];
    const float* W1    = (const float*)d_in[15];
    const float* b1    = (const float*)d_in[16];

    float* out        = (float*)d_out;
    float* out_coords = out;                         // [2048, 3]
    float* out_atoms  = out + NN * 3;                // [2048, 16]
    float* out_bonds  = out + NN * 3 + NN * NAF;     // [262144, 5]

    k_clear  <<<2048, 256>>>();
    k_scatter<<<EE / 256, 256>>>(eg);
    k_node1  <<<NN / 8, 256>>>(s, v, p, Ws, bs, Wc);
    k_mw     <<<ED + 1, 256>>>(Wb, bb, W0, b0);
    k_molmean<<<NMOL, 128>>>(batch);
    k_center <<<NN / 256, 256>>>(batch, out_coords);
    k_node2  <<<NN / 8, 256>>>(W0, Wa, ba, out_atoms);
    k_edge   <<<EE / 64, 256>>>(eg, e, W0, W1, b1, out_bonds);
}